// round 14
// baseline (speedup 1.0000x reference)
#include <cuda_runtime.h>
#include <cuda_bf16.h>
#include <math.h>
#include <cstdint>

#define CIN 64
#define COUT_PER 32
#define LALPHA 0.2f

__device__ __forceinline__ float lk(float v) { return v > 0.f ? v : LALPHA * v; }

__device__ __forceinline__ uint32_t smem_u32(const void* p) {
    uint32_t a;
    asm("{ .reg .u64 t; cvta.to.shared.u64 t, %1; cvt.u32.u64 %0, t; }" : "=r"(a) : "l"(p));
    return a;
}
__device__ __forceinline__ uint32_t pkbf(float x, float y) {
    __nv_bfloat162 h = __floats2bfloat162_rn(x, y);
    return *reinterpret_cast<uint32_t*>(&h);
}
// pack fp32 -> (lo16<<16)|hi16 split-bf16
__device__ __forceinline__ uint32_t pksp(float v) {
    __nv_bfloat16 h = __float2bfloat16(v);
    float hf = __bfloat162float(h);
    __nv_bfloat16 l = __float2bfloat16(v - hf);
    uint16_t hb = *reinterpret_cast<uint16_t*>(&h);
    uint16_t lb = *reinterpret_cast<uint16_t*>(&l);
    return ((uint32_t)lb << 16) | hb;
}
__device__ __forceinline__ uint32_t hiperm(uint32_t a, uint32_t b) { return __byte_perm(a, b, 0x5410); }
__device__ __forceinline__ uint32_t loperm(uint32_t a, uint32_t b) { return __byte_perm(a, b, 0x7632); }

#define LDSM_X4(R, ADDR) \
    asm volatile("ldmatrix.sync.aligned.m8n8.x4.shared.b16 {%0,%1,%2,%3}, [%4];" \
        : "=r"((R)[0]), "=r"((R)[1]), "=r"((R)[2]), "=r"((R)[3]) : "r"(ADDR))
#define LDSM_X2(R, ADDR) \
    asm volatile("ldmatrix.sync.aligned.m8n8.x2.shared.b16 {%0,%1}, [%2];" \
        : "=r"((R)[0]), "=r"((R)[1]) : "r"(ADDR))
#define LDSM_X2_T(R, ADDR) \
    asm volatile("ldmatrix.sync.aligned.m8n8.x2.trans.shared.b16 {%0,%1}, [%2];" \
        : "=r"((R)[0]), "=r"((R)[1]) : "r"(ADDR))
#define MMA_BF16(ACC, A, B) \
    asm volatile("mma.sync.aligned.m16n8k16.row.col.f32.bf16.bf16.f32 " \
        "{%0,%1,%2,%3}, {%4,%5,%6,%7}, {%8,%9}, {%0,%1,%2,%3};" \
        : "+f"((ACC)[0]), "+f"((ACC)[1]), "+f"((ACC)[2]), "+f"((ACC)[3]) \
        : "r"((A)[0]), "r"((A)[1]), "r"((A)[2]), "r"((A)[3]), "r"((B)[0]), "r"((B)[1]))

// ---------------- static device scratch ----------------
// compact bf16 hi/lo DFT tables; elem offs: fft32->0, fft64->1024, fft128->5120
__device__ __align__(16) __nv_bfloat16 g_Dh[21504];
__device__ __align__(16) __nv_bfloat16 g_Dl[21504];
__device__ __align__(16) __nv_bfloat16 g_Ch[21504];
__device__ __align__(16) __nv_bfloat16 g_Cl[21504];
// GT hi/lo bf16 [k][o2(64)][j(128)]; elem offs 0 / 139264 / 409600
__device__ __align__(16) __nv_bfloat16 g_Gh[942080];
__device__ __align__(16) __nv_bfloat16 g_Gl[942080];
// X packed split-bf16 [k][f][ri][c]; offs 0 / 4456448 / 8781824
__device__ __align__(16) uint32_t g_X[13041664];
// Z packed split-bf16 [f][j=2k+ri][o]; offs 0 / 2228224 / 4390912
__device__ __align__(16) uint32_t g_Z[6520832];

// ---------------- merged precompute ----------------
__global__ void k_build(const float* __restrict__ kr, const float* __restrict__ ki) {
    const int ffti = blockIdx.y;
    const int N = 32 << ffti;
    const int bins = N / 2 + 1;
    const int tid = threadIdx.x;
    if (blockIdx.x < 64) {
        // DFT tables (compact D and C, bf16 split)
        int off = (ffti == 0) ? 0 : (ffti == 1 ? 1024 : 5120);
        int total = N * N;
        int stride = 64 * 256;
        for (int idx = blockIdx.x * 256 + tid; idx < total; idx += stride) {
            {   // D compact [rp][t], ra = rp + (rp>0)
                int rp = idx / N, t = idx % N;
                int ra = rp + (rp > 0);
                int k = ra >> 1, ri = ra & 1;
                int m = (k * t) % N;
                float s, c;
                sincospif(2.0f * (float)m / (float)N, &s, &c);
                float v = ri ? -s : c;
                __nv_bfloat16 h = __float2bfloat16(v);
                g_Dh[off + idx] = h;
                g_Dl[off + idx] = __float2bfloat16(v - __bfloat162float(h));
            }
            {   // C compact [t][jj], ja = jj + (jj>0)
                int t = idx / N, jj = idx % N;
                int ja = jj + (jj > 0);
                int k = ja >> 1, ri = ja & 1;
                int m = (k * t) % N;
                float s, c;
                sincospif(2.0f * (float)m / (float)N, &s, &c);
                float w = (k == 0 || k == bins - 1) ? 1.0f : 2.0f;
                float v = (ri ? -s : c) * (w / (float)N);
                __nv_bfloat16 h = __float2bfloat16(v);
                g_Ch[off + idx] = h;
                g_Cl[off + idx] = __float2bfloat16(v - __bfloat162float(h));
            }
        }
    } else {
        // G matrices, pre-split bf16
        int goff = (ffti == 0) ? 0 : (ffti == 1 ? 139264 : 409600);
        int total = bins * CIN * COUT_PER;
        int stride = 520 * 256;
        for (int idx = (blockIdx.x - 64) * 256 + tid; idx < total; idx += stride) {
            int k = idx / (CIN * COUT_PER);
            int rem = idx % (CIN * COUT_PER);
            int c = rem / COUT_PER, o = rem % COUT_PER;
            float vr, vi;
            if (bins == 33) {
                vr = kr[k * 2048 + rem];
                vi = ki[k * 2048 + rem];
            } else {
                float src = (k + 0.5f) * (33.0f / (float)bins) - 0.5f;
                float fl = floorf(src);
                int i0 = (int)fl;
                float f = src - fl;
                int i0c = i0 < 0 ? 0 : i0;
                int i1c = i0 + 1 > 32 ? 32 : i0 + 1;
                vr = (1.0f - f) * kr[i0c * 2048 + rem] + f * kr[i1c * 2048 + rem];
                vi = (1.0f - f) * ki[i0c * 2048 + rem] + f * ki[i1c * 2048 + rem];
            }
            int base = goff + k * 8192;
            auto st = [&](int pos, float v) {
                __nv_bfloat16 h = __float2bfloat16(v);
                g_Gh[pos] = h;
                g_Gl[pos] = __float2bfloat16(v - __bfloat162float(h));
            };
            st(base + (2 * o) * 128 + c, vr);
            st(base + (2 * o + 1) * 128 + c, vi);
            st(base + (2 * o) * 128 + 64 + c, -vi);
            st(base + (2 * o + 1) * 128 + 64 + c, vr);
        }
    }
}

// ---------------- stage 1 body: forward DFT via mma.sync ----------------
template <int N, int DOFF, int XOFF, int F>
__device__ __forceinline__ void stage1_body(const float* __restrict__ x) {
    constexpr int RG = N / 16;
    constexpr int FR = 128 / N;
    constexpr int SDD = N + 8;
    constexpr int SDX = 72;
    extern __shared__ char smem[];
    __nv_bfloat16* Dh = reinterpret_cast<__nv_bfloat16*>(smem);
    __nv_bfloat16* Dl = Dh + N * SDD;
    __nv_bfloat16* Xh = Dl + N * SDD;
    __nv_bfloat16* Xl = Xh + 128 * SDX;

    const int tid = threadIdx.x;
    const int warp = tid >> 5, lane = tid & 31;
    const int f0 = blockIdx.x * FR;

    const uint4* DhG = reinterpret_cast<const uint4*>(g_Dh + DOFF);
    const uint4* DlG = reinterpret_cast<const uint4*>(g_Dl + DOFF);
    for (int idx = tid; idx < N * N / 8; idx += 256) {
        int e = idx * 8;
        int row = e / N, col = e % N;
        *reinterpret_cast<uint4*>(&Dh[row * SDD + col]) = DhG[idx];
        *reinterpret_cast<uint4*>(&Dl[row * SDD + col]) = DlG[idx];
    }
    const float4* xg = reinterpret_cast<const float4*>(x + (size_t)f0 * N * 64);
    for (int idx = tid; idx < 2048; idx += 256) {
        int row = idx >> 4, q = idx & 15;
        float4 v = xg[idx];
        float hx = __bfloat162float(__float2bfloat16(v.x));
        float hy = __bfloat162float(__float2bfloat16(v.y));
        float hz = __bfloat162float(__float2bfloat16(v.z));
        float hw = __bfloat162float(__float2bfloat16(v.w));
        *reinterpret_cast<uint2*>(&Xh[row * SDX + 4 * q]) =
            make_uint2(pkbf(v.x, v.y), pkbf(v.z, v.w));
        *reinterpret_cast<uint2*>(&Xl[row * SDX + 4 * q]) =
            make_uint2(pkbf(v.x - hx, v.y - hy), pkbf(v.z - hz, v.w - hw));
    }
    __syncthreads();

    const int fr = warp / RG, rg = warp % RG;
    const int m0 = rg * 16;

    float acc[8][4];
#pragma unroll
    for (int nt = 0; nt < 8; nt++)
#pragma unroll
        for (int q = 0; q < 4; q++) acc[nt][q] = 0.f;

    const uint32_t aH = smem_u32(Dh) + 2u * ((m0 + (lane & 15)) * SDD + ((lane >> 4) << 3));
    const uint32_t aL = aH + 2u * N * SDD;
    const uint32_t bH = smem_u32(Xh) + 2u * ((fr * N + (lane & 15)) * SDX);
    const uint32_t bL = bH + 2u * 128 * SDX;

#pragma unroll
    for (int kc = 0; kc < N / 16; kc++) {
        uint32_t ah[4], al[4];
        LDSM_X4(ah, aH + kc * 32);
        LDSM_X4(al, aL + kc * 32);
#pragma unroll
        for (int nt = 0; nt < 8; nt++) {
            uint32_t bh[2], bl[2];
            LDSM_X2_T(bh, bH + (uint32_t)(kc * 32 * SDX) + nt * 16);
            LDSM_X2_T(bl, bL + (uint32_t)(kc * 32 * SDX) + nt * 16);
            MMA_BF16(acc[nt], ah, bh);
            MMA_BF16(acc[nt], ah, bl);
            MMA_BF16(acc[nt], al, bh);
        }
    }

    // epilogue: pack split-bf16 into X
    {
        const int f = f0 + fr;
        const int rp0 = m0 + (lane >> 2);
        const int c0 = 2 * (lane & 3);
#pragma unroll
        for (int nt = 0; nt < 8; nt++) {
            int c = nt * 8 + c0;
            {
                int ra = rp0 + (rp0 > 0);
                int k = ra >> 1, ri = ra & 1;
                *reinterpret_cast<uint2*>(
                    g_X + XOFF + ((size_t)(k * F + f) * 2 + ri) * 64 + c) =
                    make_uint2(pksp(acc[nt][0]), pksp(acc[nt][1]));
            }
            {
                int rp = rp0 + 8;
                int ra = rp + (rp > 0);
                int k = ra >> 1, ri = ra & 1;
                *reinterpret_cast<uint2*>(
                    g_X + XOFF + ((size_t)(k * F + f) * 2 + ri) * 64 + c) =
                    make_uint2(pksp(acc[nt][2]), pksp(acc[nt][3]));
            }
        }
    }

    if (tid < FR * 32) {
        int fr2 = tid >> 5, m = tid & 31;
        int kz = (m >> 4) ? (N / 2) : 0;
        int q = m & 15;
        *reinterpret_cast<uint4*>(
            g_X + XOFF + ((size_t)(kz * F + f0 + fr2) * 2 + 1) * 64 + 4 * q) =
            make_uint4(0u, 0u, 0u, 0u);
    }
}

__global__ __launch_bounds__(256) void k_stage1_a(const float* __restrict__ x) {
    if (blockIdx.y == 0) stage1_body<32, 0, 0, 2048>(x);
    else stage1_body<64, 1024, 4456448, 1024>(x);
}
__global__ __launch_bounds__(256) void k_stage1_b(const float* __restrict__ x) {
    stage1_body<128, 5120, 8781824, 512>(x);
}

// ---------------- stage 2: merged mma.sync kernel over all ffts ----------------
__global__ __launch_bounds__(256) void k_stage2_tc() {
    constexpr int SDB = 136;
    extern __shared__ char smem[];
    __nv_bfloat16* Ah = reinterpret_cast<__nv_bfloat16*>(smem);
    __nv_bfloat16* Al = Ah + 128 * SDB;
    __nv_bfloat16* Bh = Al + 128 * SDB;
    __nv_bfloat16* Bl = Bh + 64 * SDB;

    const int tid = threadIdx.x;
    const int warp = tid >> 5, lane = tid & 31;

    // segment decode: 16x17 | 8x33 | 4x65
    int b = blockIdx.x;
    int xoff, goff, zoff, F, bins, fb, k;
    if (b < 272) {
        fb = b / 17; k = b % 17;
        xoff = 0; goff = 0; zoff = 0; F = 2048; bins = 17;
    } else if (b < 536) {
        int t = b - 272;
        fb = t / 33; k = t % 33;
        xoff = 4456448; goff = 139264; zoff = 2228224; F = 1024; bins = 33;
    } else {
        int t = b - 536;
        fb = t / 65; k = t % 65;
        xoff = 8781824; goff = 409600; zoff = 4390912; F = 512; bins = 65;
    }
    const int f0 = fb * 128;

    // A: unpack packed split-bf16 X rows
    const uint4* Xg = reinterpret_cast<const uint4*>(g_X + xoff + ((size_t)k * F + f0) * 128);
    for (int idx = tid; idx < 128 * 32; idx += 256) {
        int row = idx >> 5, q = idx & 31;
        uint4 p = Xg[idx];
        *reinterpret_cast<uint2*>(&Ah[row * SDB + 4 * q]) =
            make_uint2(hiperm(p.x, p.y), hiperm(p.z, p.w));
        *reinterpret_cast<uint2*>(&Al[row * SDB + 4 * q]) =
            make_uint2(loperm(p.x, p.y), loperm(p.z, p.w));
    }
    // B: straight copy of pre-split G
    const uint4* GhG = reinterpret_cast<const uint4*>(g_Gh + goff + (size_t)k * 8192);
    const uint4* GlG = reinterpret_cast<const uint4*>(g_Gl + goff + (size_t)k * 8192);
    for (int idx = tid; idx < 64 * 16; idx += 256) {
        int row = idx >> 4, q = idx & 15;
        *reinterpret_cast<uint4*>(&Bh[row * SDB + 8 * q]) = GhG[idx];
        *reinterpret_cast<uint4*>(&Bl[row * SDB + 8 * q]) = GlG[idx];
    }
    __syncthreads();

    const int m0 = warp * 16;
    float acc[8][4];
#pragma unroll
    for (int nt = 0; nt < 8; nt++)
#pragma unroll
        for (int q = 0; q < 4; q++) acc[nt][q] = 0.f;

    const uint32_t aoff = (uint32_t)((m0 + (lane & 15)) * SDB + ((lane >> 4) << 3));
    const uint32_t a_addr_h = smem_u32(Ah) + 2 * aoff;
    const uint32_t a_addr_l = smem_u32(Al) + 2 * aoff;
    const uint32_t boff = (uint32_t)((lane & 7) * SDB + (((lane >> 3) & 1) << 3));
    const uint32_t b_addr_h = smem_u32(Bh) + 2 * boff;
    const uint32_t b_addr_l = smem_u32(Bl) + 2 * boff;

#pragma unroll
    for (int kc = 0; kc < 8; kc++) {
        uint32_t ah[4], al[4];
        LDSM_X4(ah, a_addr_h + 32 * kc);
        LDSM_X4(al, a_addr_l + 32 * kc);
#pragma unroll
        for (int nt = 0; nt < 8; nt++) {
            uint32_t bh[2], bl[2];
            LDSM_X2(bh, b_addr_h + (uint32_t)(nt * 8 * SDB * 2) + 32 * kc);
            LDSM_X2(bl, b_addr_l + (uint32_t)(nt * 8 * SDB * 2) + 32 * kc);
            MMA_BF16(acc[nt], ah, bh);
            MMA_BF16(acc[nt], ah, bl);
            MMA_BF16(acc[nt], al, bh);
        }
    }

    // epilogue: leaky + pack split-bf16 into Z
    {
        const int o = (lane & 3);
        const int r0 = f0 + m0 + (lane >> 2);
        uint32_t* zp0 = g_Z + zoff + ((size_t)r0 * bins + k) * 64;
        uint32_t* zp1 = g_Z + zoff + ((size_t)(r0 + 8) * bins + k) * 64;
#pragma unroll
        for (int nt = 0; nt < 8; nt++) {
            int oo = nt * 4 + o;
            zp0[oo]      = pksp(lk(acc[nt][0]));
            zp0[32 + oo] = pksp(lk(acc[nt][1]));
            zp1[oo]      = pksp(lk(acc[nt][2]));
            zp1[32 + oo] = pksp(lk(acc[nt][3]));
        }
    }
}

// ---------------- stage 3 body: irfft + bias via mma.sync ----------------
template <int N, int COFF, int ZOFF, int OOFF>
__device__ __forceinline__ void stage3_body(float* __restrict__ out, const float* __restrict__ bias) {
    constexpr int BINS = N / 2 + 1;
    constexpr int RG = N / 16;
    constexpr int FR = 128 / N;
    constexpr int SDD = N + 8;
    constexpr int SDZ = 40;
    extern __shared__ char smem[];
    __nv_bfloat16* Ch = reinterpret_cast<__nv_bfloat16*>(smem);
    __nv_bfloat16* Cl = Ch + N * SDD;
    __nv_bfloat16* Zh = Cl + N * SDD;
    __nv_bfloat16* Zl = Zh + 128 * SDZ;

    const int tid = threadIdx.x;
    const int warp = tid >> 5, lane = tid & 31;
    const int f0 = blockIdx.x * FR;

    const uint4* ChG = reinterpret_cast<const uint4*>(g_Ch + COFF);
    const uint4* ClG = reinterpret_cast<const uint4*>(g_Cl + COFF);
    for (int idx = tid; idx < N * N / 8; idx += 256) {
        int e = idx * 8;
        int row = e / N, col = e % N;
        *reinterpret_cast<uint4*>(&Ch[row * SDD + col]) = ChG[idx];
        *reinterpret_cast<uint4*>(&Cl[row * SDD + col]) = ClG[idx];
    }
    // unpack packed Z with zero-col remap
    for (int idx = tid; idx < 1024; idx += 256) {
        int row = idx >> 3, q = idx & 7;
        int fr = row / N, jj = row % N;
        int ja = jj + (jj > 0);
        uint4 p = *reinterpret_cast<const uint4*>(
            g_Z + ZOFF + (size_t)(f0 + fr) * (BINS * 64) + ja * 32 + 4 * q);
        *reinterpret_cast<uint2*>(&Zh[row * SDZ + 4 * q]) =
            make_uint2(hiperm(p.x, p.y), hiperm(p.z, p.w));
        *reinterpret_cast<uint2*>(&Zl[row * SDZ + 4 * q]) =
            make_uint2(loperm(p.x, p.y), loperm(p.z, p.w));
    }
    __syncthreads();

    const int fr = warp / RG, rg = warp % RG;
    const int m0 = rg * 16;

    float acc[4][4];
#pragma unroll
    for (int nt = 0; nt < 4; nt++)
#pragma unroll
        for (int q = 0; q < 4; q++) acc[nt][q] = 0.f;

    const uint32_t aH = smem_u32(Ch) + 2u * ((m0 + (lane & 15)) * SDD + ((lane >> 4) << 3));
    const uint32_t aL = aH + 2u * N * SDD;
    const uint32_t bH = smem_u32(Zh) + 2u * ((fr * N + (lane & 15)) * SDZ);
    const uint32_t bL = bH + 2u * 128 * SDZ;

#pragma unroll
    for (int kc = 0; kc < N / 16; kc++) {
        uint32_t ah[4], al[4];
        LDSM_X4(ah, aH + kc * 32);
        LDSM_X4(al, aL + kc * 32);
#pragma unroll
        for (int nt = 0; nt < 4; nt++) {
            uint32_t bh[2], bl[2];
            LDSM_X2_T(bh, bH + (uint32_t)(kc * 32 * SDZ) + nt * 16);
            LDSM_X2_T(bl, bL + (uint32_t)(kc * 32 * SDZ) + nt * 16);
            MMA_BF16(acc[nt], ah, bh);
            MMA_BF16(acc[nt], ah, bl);
            MMA_BF16(acc[nt], al, bh);
        }
    }

    {
        const int f = f0 + fr;
        const int t0 = m0 + (lane >> 2);
        const int c0 = 2 * (lane & 3);
#pragma unroll
        for (int nt = 0; nt < 4; nt++) {
            int o = nt * 8 + c0;
            float2 bv = *reinterpret_cast<const float2*>(bias + OOFF + o);
            *reinterpret_cast<float2*>(out + ((size_t)f * N + t0) * 96 + OOFF + o) =
                make_float2(acc[nt][0] + bv.x, acc[nt][1] + bv.y);
            *reinterpret_cast<float2*>(out + ((size_t)f * N + t0 + 8) * 96 + OOFF + o) =
                make_float2(acc[nt][2] + bv.x, acc[nt][3] + bv.y);
        }
    }
}

__global__ __launch_bounds__(256) void k_stage3_a(float* __restrict__ out, const float* __restrict__ bias) {
    if (blockIdx.y == 0) stage3_body<32, 0, 0, 0>(out, bias);
    else stage3_body<64, 1024, 2228224, 32>(out, bias);
}
__global__ __launch_bounds__(256) void k_stage3_b(float* __restrict__ out, const float* __restrict__ bias) {
    stage3_body<128, 5120, 4390912, 64>(out, bias);
}

// ---------------- launch ----------------
extern "C" void kernel_launch(void* const* d_in, const int* in_sizes, int n_in,
                              void* d_out, int out_size) {
    const float* x    = (const float*)d_in[0];
    const float* kr   = (const float*)d_in[1];
    const float* ki   = (const float*)d_in[2];
    const float* bias = (const float*)d_in[3];
    float* out = (float*)d_out;

    const int s1_a = (2 * 64 * 72 + 2 * 128 * 72) * 2;    // 55296
    const int s1_b = (2 * 128 * 136 + 2 * 128 * 72) * 2;  // 106496
    const int s2   = (128 * 136 * 2 + 64 * 136 * 2) * 2;  // 104448
    const int s3_a = (2 * 64 * 72 + 2 * 128 * 40) * 2;    // 38912
    const int s3_b = (2 * 128 * 136 + 2 * 128 * 40) * 2;  // 90112

    cudaFuncSetAttribute(k_stage1_a, cudaFuncAttributeMaxDynamicSharedMemorySize, s1_a);
    cudaFuncSetAttribute(k_stage1_b, cudaFuncAttributeMaxDynamicSharedMemorySize, s1_b);
    cudaFuncSetAttribute(k_stage2_tc, cudaFuncAttributeMaxDynamicSharedMemorySize, s2);
    cudaFuncSetAttribute(k_stage3_a, cudaFuncAttributeMaxDynamicSharedMemorySize, s3_a);
    cudaFuncSetAttribute(k_stage3_b, cudaFuncAttributeMaxDynamicSharedMemorySize, s3_b);

    k_build<<<dim3(584, 3), 256>>>(kr, ki);

    k_stage1_a<<<dim3(512, 2), 256, s1_a>>>(x);
    k_stage1_b<<<512, 256, s1_b>>>(x);

    k_stage2_tc<<<796, 256, s2>>>();

    k_stage3_a<<<dim3(512, 2), 256, s3_a>>>(out, bias);
    k_stage3_b<<<512, 256, s3_b>>>(out, bias);
}

// round 15
// speedup vs baseline: 1.0827x; 1.0827x over previous
#include <cuda_runtime.h>
#include <cuda_bf16.h>
#include <math.h>
#include <cstdint>

#define CIN 64
#define COUT_PER 32
#define LALPHA 0.2f

__device__ __forceinline__ float lk(float v) { return v > 0.f ? v : LALPHA * v; }

__device__ __forceinline__ uint32_t smem_u32(const void* p) {
    uint32_t a;
    asm("{ .reg .u64 t; cvta.to.shared.u64 t, %1; cvt.u32.u64 %0, t; }" : "=r"(a) : "l"(p));
    return a;
}
__device__ __forceinline__ uint32_t pkbf(float x, float y) {
    __nv_bfloat162 h = __floats2bfloat162_rn(x, y);
    return *reinterpret_cast<uint32_t*>(&h);
}
// pack fp32 -> (lo16<<16)|hi16 split-bf16
__device__ __forceinline__ uint32_t pksp(float v) {
    __nv_bfloat16 h = __float2bfloat16(v);
    float hf = __bfloat162float(h);
    __nv_bfloat16 l = __float2bfloat16(v - hf);
    uint16_t hb = *reinterpret_cast<uint16_t*>(&h);
    uint16_t lb = *reinterpret_cast<uint16_t*>(&l);
    return ((uint32_t)lb << 16) | hb;
}
__device__ __forceinline__ uint32_t hiperm(uint32_t a, uint32_t b) { return __byte_perm(a, b, 0x5410); }
__device__ __forceinline__ uint32_t loperm(uint32_t a, uint32_t b) { return __byte_perm(a, b, 0x7632); }

#define LDSM_X4(R, ADDR) \
    asm volatile("ldmatrix.sync.aligned.m8n8.x4.shared.b16 {%0,%1,%2,%3}, [%4];" \
        : "=r"((R)[0]), "=r"((R)[1]), "=r"((R)[2]), "=r"((R)[3]) : "r"(ADDR))
#define LDSM_X2(R, ADDR) \
    asm volatile("ldmatrix.sync.aligned.m8n8.x2.shared.b16 {%0,%1}, [%2];" \
        : "=r"((R)[0]), "=r"((R)[1]) : "r"(ADDR))
#define LDSM_X2_T(R, ADDR) \
    asm volatile("ldmatrix.sync.aligned.m8n8.x2.trans.shared.b16 {%0,%1}, [%2];" \
        : "=r"((R)[0]), "=r"((R)[1]) : "r"(ADDR))
#define MMA_BF16(ACC, A, B) \
    asm volatile("mma.sync.aligned.m16n8k16.row.col.f32.bf16.bf16.f32 " \
        "{%0,%1,%2,%3}, {%4,%5,%6,%7}, {%8,%9}, {%0,%1,%2,%3};" \
        : "+f"((ACC)[0]), "+f"((ACC)[1]), "+f"((ACC)[2]), "+f"((ACC)[3]) \
        : "r"((A)[0]), "r"((A)[1]), "r"((A)[2]), "r"((A)[3]), "r"((B)[0]), "r"((B)[1]))

// ---------------- static device scratch ----------------
// compact bf16 hi/lo DFT tables; elem offs: fft32->0, fft64->1024, fft128->5120
__device__ __align__(16) __nv_bfloat16 g_Dh[21504];
__device__ __align__(16) __nv_bfloat16 g_Dl[21504];
__device__ __align__(16) __nv_bfloat16 g_Ch[21504];
__device__ __align__(16) __nv_bfloat16 g_Cl[21504];
// GT hi/lo bf16 [k][o2(64)][j(128)]; elem offs 0 / 139264 / 409600
__device__ __align__(16) __nv_bfloat16 g_Gh[942080];
__device__ __align__(16) __nv_bfloat16 g_Gl[942080];
// X packed split-bf16 [k][f][ri][c]; offs 0 / 4456448 / 8781824
__device__ __align__(16) uint32_t g_X[13041664];
// Z packed split-bf16 [f][j=2k+ri][o]; offs 0 / 2228224 / 4390912
__device__ __align__(16) uint32_t g_Z[6520832];

// ---------------- merged precompute ----------------
__global__ void k_build(const float* __restrict__ kr, const float* __restrict__ ki) {
    const int ffti = blockIdx.y;
    const int N = 32 << ffti;
    const int bins = N / 2 + 1;
    const int tid = threadIdx.x;
    if (blockIdx.x < 64) {
        int off = (ffti == 0) ? 0 : (ffti == 1 ? 1024 : 5120);
        int total = N * N;
        int stride = 64 * 256;
        for (int idx = blockIdx.x * 256 + tid; idx < total; idx += stride) {
            {   // D compact [rp][t], ra = rp + (rp>0)
                int rp = idx / N, t = idx % N;
                int ra = rp + (rp > 0);
                int k = ra >> 1, ri = ra & 1;
                int m = (k * t) % N;
                float s, c;
                sincospif(2.0f * (float)m / (float)N, &s, &c);
                float v = ri ? -s : c;
                __nv_bfloat16 h = __float2bfloat16(v);
                g_Dh[off + idx] = h;
                g_Dl[off + idx] = __float2bfloat16(v - __bfloat162float(h));
            }
            {   // C compact [t][jj], ja = jj + (jj>0)
                int t = idx / N, jj = idx % N;
                int ja = jj + (jj > 0);
                int k = ja >> 1, ri = ja & 1;
                int m = (k * t) % N;
                float s, c;
                sincospif(2.0f * (float)m / (float)N, &s, &c);
                float w = (k == 0 || k == bins - 1) ? 1.0f : 2.0f;
                float v = (ri ? -s : c) * (w / (float)N);
                __nv_bfloat16 h = __float2bfloat16(v);
                g_Ch[off + idx] = h;
                g_Cl[off + idx] = __float2bfloat16(v - __bfloat162float(h));
            }
        }
    } else {
        int goff = (ffti == 0) ? 0 : (ffti == 1 ? 139264 : 409600);
        int total = bins * CIN * COUT_PER;
        int stride = 520 * 256;
        for (int idx = (blockIdx.x - 64) * 256 + tid; idx < total; idx += stride) {
            int k = idx / (CIN * COUT_PER);
            int rem = idx % (CIN * COUT_PER);
            int c = rem / COUT_PER, o = rem % COUT_PER;
            float vr, vi;
            if (bins == 33) {
                vr = kr[k * 2048 + rem];
                vi = ki[k * 2048 + rem];
            } else {
                float src = (k + 0.5f) * (33.0f / (float)bins) - 0.5f;
                float fl = floorf(src);
                int i0 = (int)fl;
                float f = src - fl;
                int i0c = i0 < 0 ? 0 : i0;
                int i1c = i0 + 1 > 32 ? 32 : i0 + 1;
                vr = (1.0f - f) * kr[i0c * 2048 + rem] + f * kr[i1c * 2048 + rem];
                vi = (1.0f - f) * ki[i0c * 2048 + rem] + f * ki[i1c * 2048 + rem];
            }
            int base = goff + k * 8192;
            auto st = [&](int pos, float v) {
                __nv_bfloat16 h = __float2bfloat16(v);
                g_Gh[pos] = h;
                g_Gl[pos] = __float2bfloat16(v - __bfloat162float(h));
            };
            st(base + (2 * o) * 128 + c, vr);
            st(base + (2 * o + 1) * 128 + c, vi);
            st(base + (2 * o) * 128 + 64 + c, -vi);
            st(base + (2 * o + 1) * 128 + 64 + c, vr);
        }
    }
}

// ---------------- stage 1 body: forward DFT via mma.sync ----------------
template <int N, int DOFF, int XOFF, int F>
__device__ __forceinline__ void stage1_body(const float* __restrict__ x) {
    constexpr int RG = N / 16;
    constexpr int FR = 128 / N;
    constexpr int SDD = N + 8;
    constexpr int SDX = 72;
    extern __shared__ char smem[];
    __nv_bfloat16* Dh = reinterpret_cast<__nv_bfloat16*>(smem);
    __nv_bfloat16* Dl = Dh + N * SDD;
    __nv_bfloat16* Xh = Dl + N * SDD;
    __nv_bfloat16* Xl = Xh + 128 * SDX;

    const int tid = threadIdx.x;
    const int warp = tid >> 5, lane = tid & 31;
    const int f0 = blockIdx.x * FR;

    const uint4* DhG = reinterpret_cast<const uint4*>(g_Dh + DOFF);
    const uint4* DlG = reinterpret_cast<const uint4*>(g_Dl + DOFF);
    for (int idx = tid; idx < N * N / 8; idx += 256) {
        int e = idx * 8;
        int row = e / N, col = e % N;
        *reinterpret_cast<uint4*>(&Dh[row * SDD + col]) = DhG[idx];
        *reinterpret_cast<uint4*>(&Dl[row * SDD + col]) = DlG[idx];
    }
    const float4* xg = reinterpret_cast<const float4*>(x + (size_t)f0 * N * 64);
    for (int idx = tid; idx < 2048; idx += 256) {
        int row = idx >> 4, q = idx & 15;
        float4 v = xg[idx];
        float hx = __bfloat162float(__float2bfloat16(v.x));
        float hy = __bfloat162float(__float2bfloat16(v.y));
        float hz = __bfloat162float(__float2bfloat16(v.z));
        float hw = __bfloat162float(__float2bfloat16(v.w));
        *reinterpret_cast<uint2*>(&Xh[row * SDX + 4 * q]) =
            make_uint2(pkbf(v.x, v.y), pkbf(v.z, v.w));
        *reinterpret_cast<uint2*>(&Xl[row * SDX + 4 * q]) =
            make_uint2(pkbf(v.x - hx, v.y - hy), pkbf(v.z - hz, v.w - hw));
    }
    __syncthreads();

    const int fr = warp / RG, rg = warp % RG;
    const int m0 = rg * 16;

    float acc[8][4];
#pragma unroll
    for (int nt = 0; nt < 8; nt++)
#pragma unroll
        for (int q = 0; q < 4; q++) acc[nt][q] = 0.f;

    const uint32_t aH = smem_u32(Dh) + 2u * ((m0 + (lane & 15)) * SDD + ((lane >> 4) << 3));
    const uint32_t aL = aH + 2u * N * SDD;
    const uint32_t bH = smem_u32(Xh) + 2u * ((fr * N + (lane & 15)) * SDX);
    const uint32_t bL = bH + 2u * 128 * SDX;

#pragma unroll
    for (int kc = 0; kc < N / 16; kc++) {
        uint32_t ah[4], al[4];
        LDSM_X4(ah, aH + kc * 32);
        LDSM_X4(al, aL + kc * 32);
#pragma unroll
        for (int nt = 0; nt < 8; nt++) {
            uint32_t bh[2], bl[2];
            LDSM_X2_T(bh, bH + (uint32_t)(kc * 32 * SDX) + nt * 16);
            LDSM_X2_T(bl, bL + (uint32_t)(kc * 32 * SDX) + nt * 16);
            MMA_BF16(acc[nt], ah, bh);
            MMA_BF16(acc[nt], ah, bl);
            MMA_BF16(acc[nt], al, bh);
        }
    }

    // epilogue: pack split-bf16 into X
    {
        const int f = f0 + fr;
        const int rp0 = m0 + (lane >> 2);
        const int c0 = 2 * (lane & 3);
#pragma unroll
        for (int nt = 0; nt < 8; nt++) {
            int c = nt * 8 + c0;
            {
                int ra = rp0 + (rp0 > 0);
                int k = ra >> 1, ri = ra & 1;
                *reinterpret_cast<uint2*>(
                    g_X + XOFF + ((size_t)(k * F + f) * 2 + ri) * 64 + c) =
                    make_uint2(pksp(acc[nt][0]), pksp(acc[nt][1]));
            }
            {
                int rp = rp0 + 8;
                int ra = rp + (rp > 0);
                int k = ra >> 1, ri = ra & 1;
                *reinterpret_cast<uint2*>(
                    g_X + XOFF + ((size_t)(k * F + f) * 2 + ri) * 64 + c) =
                    make_uint2(pksp(acc[nt][2]), pksp(acc[nt][3]));
            }
        }
    }

    if (tid < FR * 32) {
        int fr2 = tid >> 5, m = tid & 31;
        int kz = (m >> 4) ? (N / 2) : 0;
        int q = m & 15;
        *reinterpret_cast<uint4*>(
            g_X + XOFF + ((size_t)(kz * F + f0 + fr2) * 2 + 1) * 64 + 4 * q) =
            make_uint4(0u, 0u, 0u, 0u);
    }
}

__global__ __launch_bounds__(256) void k_stage1_a(const float* __restrict__ x) {
    if (blockIdx.y == 0) stage1_body<32, 0, 0, 2048>(x);
    else stage1_body<64, 1024, 4456448, 1024>(x);
}
__global__ __launch_bounds__(256) void k_stage1_b(const float* __restrict__ x) {
    stage1_body<128, 5120, 8781824, 512>(x);
}

// ---------------- stage 2: mma.sync, A fragments direct from global ----------------
__global__ __launch_bounds__(256) void k_stage2_tc() {
    constexpr int SDB = 136;
    extern __shared__ char smem[];
    __nv_bfloat16* Bh = reinterpret_cast<__nv_bfloat16*>(smem);
    __nv_bfloat16* Bl = Bh + 64 * SDB;

    const int tid = threadIdx.x;
    const int warp = tid >> 5, lane = tid & 31;

    // segment decode: 16x17 | 8x33 | 4x65
    int b = blockIdx.x;
    int xoff, goff, zoff, F, bins, fb, k;
    if (b < 272) {
        fb = b / 17; k = b % 17;
        xoff = 0; goff = 0; zoff = 0; F = 2048; bins = 17;
    } else if (b < 536) {
        int t = b - 272;
        fb = t / 33; k = t % 33;
        xoff = 4456448; goff = 139264; zoff = 2228224; F = 1024; bins = 33;
    } else {
        int t = b - 536;
        fb = t / 65; k = t % 65;
        xoff = 8781824; goff = 409600; zoff = 4390912; F = 512; bins = 65;
    }
    const int f0 = fb * 128;

    // B: straight copy of pre-split G into smem (shared by all 8 warps)
    const uint4* GhG = reinterpret_cast<const uint4*>(g_Gh + goff + (size_t)k * 8192);
    const uint4* GlG = reinterpret_cast<const uint4*>(g_Gl + goff + (size_t)k * 8192);
    for (int idx = tid; idx < 64 * 16; idx += 256) {
        int row = idx >> 4, q = idx & 15;
        *reinterpret_cast<uint4*>(&Bh[row * SDB + 8 * q]) = GhG[idx];
        *reinterpret_cast<uint4*>(&Bl[row * SDB + 8 * q]) = GlG[idx];
    }
    __syncthreads();

    const int m0 = warp * 16;
    float acc[8][4];
#pragma unroll
    for (int nt = 0; nt < 8; nt++)
#pragma unroll
        for (int q = 0; q < 4; q++) acc[nt][q] = 0.f;

    // A fragment source rows in g_X (packed split-bf16):
    //   a0/a2: row m0 + lane/4 ; a1/a3: +8 ; cols 16*kc + 2*(lane%4) (+8)
    const uint32_t* Arow0 = g_X + xoff + ((size_t)k * F + f0 + m0 + (lane >> 2)) * 128 + 2 * (lane & 3);
    const uint32_t* Arow1 = Arow0 + 8 * 128;

    const uint32_t boff = (uint32_t)((lane & 7) * SDB + (((lane >> 3) & 1) << 3));
    const uint32_t b_addr_h = smem_u32(Bh) + 2 * boff;
    const uint32_t b_addr_l = smem_u32(Bl) + 2 * boff;

    uint2 p[4];
    p[0] = *reinterpret_cast<const uint2*>(Arow0);
    p[1] = *reinterpret_cast<const uint2*>(Arow1);
    p[2] = *reinterpret_cast<const uint2*>(Arow0 + 8);
    p[3] = *reinterpret_cast<const uint2*>(Arow1 + 8);

#pragma unroll
    for (int kc = 0; kc < 8; kc++) {
        uint32_t ah[4], al[4];
#pragma unroll
        for (int q = 0; q < 4; q++) {
            ah[q] = hiperm(p[q].x, p[q].y);
            al[q] = loperm(p[q].x, p[q].y);
        }
        if (kc < 7) {
            p[0] = *reinterpret_cast<const uint2*>(Arow0 + 16 * (kc + 1));
            p[1] = *reinterpret_cast<const uint2*>(Arow1 + 16 * (kc + 1));
            p[2] = *reinterpret_cast<const uint2*>(Arow0 + 16 * (kc + 1) + 8);
            p[3] = *reinterpret_cast<const uint2*>(Arow1 + 16 * (kc + 1) + 8);
        }
#pragma unroll
        for (int nt = 0; nt < 8; nt++) {
            uint32_t bh[2], bl[2];
            LDSM_X2(bh, b_addr_h + (uint32_t)(nt * 8 * SDB * 2) + 32 * kc);
            LDSM_X2(bl, b_addr_l + (uint32_t)(nt * 8 * SDB * 2) + 32 * kc);
            MMA_BF16(acc[nt], ah, bh);
            MMA_BF16(acc[nt], ah, bl);
            MMA_BF16(acc[nt], al, bh);
        }
    }

    // epilogue: leaky + pack split-bf16 into Z
    {
        const int o = (lane & 3);
        const int r0 = f0 + m0 + (lane >> 2);
        uint32_t* zp0 = g_Z + zoff + ((size_t)r0 * bins + k) * 64;
        uint32_t* zp1 = g_Z + zoff + ((size_t)(r0 + 8) * bins + k) * 64;
#pragma unroll
        for (int nt = 0; nt < 8; nt++) {
            int oo = nt * 4 + o;
            zp0[oo]      = pksp(lk(acc[nt][0]));
            zp0[32 + oo] = pksp(lk(acc[nt][1]));
            zp1[oo]      = pksp(lk(acc[nt][2]));
            zp1[32 + oo] = pksp(lk(acc[nt][3]));
        }
    }
}

// ---------------- stage 3 body: irfft + bias via mma.sync ----------------
template <int N, int COFF, int ZOFF, int OOFF>
__device__ __forceinline__ void stage3_body(float* __restrict__ out, const float* __restrict__ bias) {
    constexpr int BINS = N / 2 + 1;
    constexpr int RG = N / 16;
    constexpr int FR = 128 / N;
    constexpr int SDD = N + 8;
    constexpr int SDZ = 40;
    extern __shared__ char smem[];
    __nv_bfloat16* Ch = reinterpret_cast<__nv_bfloat16*>(smem);
    __nv_bfloat16* Cl = Ch + N * SDD;
    __nv_bfloat16* Zh = Cl + N * SDD;
    __nv_bfloat16* Zl = Zh + 128 * SDZ;

    const int tid = threadIdx.x;
    const int warp = tid >> 5, lane = tid & 31;
    const int f0 = blockIdx.x * FR;

    const uint4* ChG = reinterpret_cast<const uint4*>(g_Ch + COFF);
    const uint4* ClG = reinterpret_cast<const uint4*>(g_Cl + COFF);
    for (int idx = tid; idx < N * N / 8; idx += 256) {
        int e = idx * 8;
        int row = e / N, col = e % N;
        *reinterpret_cast<uint4*>(&Ch[row * SDD + col]) = ChG[idx];
        *reinterpret_cast<uint4*>(&Cl[row * SDD + col]) = ClG[idx];
    }
    // unpack packed Z with zero-col remap
    for (int idx = tid; idx < 1024; idx += 256) {
        int row = idx >> 3, q = idx & 7;
        int fr = row / N, jj = row % N;
        int ja = jj + (jj > 0);
        uint4 p = *reinterpret_cast<const uint4*>(
            g_Z + ZOFF + (size_t)(f0 + fr) * (BINS * 64) + ja * 32 + 4 * q);
        *reinterpret_cast<uint2*>(&Zh[row * SDZ + 4 * q]) =
            make_uint2(hiperm(p.x, p.y), hiperm(p.z, p.w));
        *reinterpret_cast<uint2*>(&Zl[row * SDZ + 4 * q]) =
            make_uint2(loperm(p.x, p.y), loperm(p.z, p.w));
    }
    __syncthreads();

    const int fr = warp / RG, rg = warp % RG;
    const int m0 = rg * 16;

    float acc[4][4];
#pragma unroll
    for (int nt = 0; nt < 4; nt++)
#pragma unroll
        for (int q = 0; q < 4; q++) acc[nt][q] = 0.f;

    const uint32_t aH = smem_u32(Ch) + 2u * ((m0 + (lane & 15)) * SDD + ((lane >> 4) << 3));
    const uint32_t aL = aH + 2u * N * SDD;
    const uint32_t bH = smem_u32(Zh) + 2u * ((fr * N + (lane & 15)) * SDZ);
    const uint32_t bL = bH + 2u * 128 * SDZ;

#pragma unroll
    for (int kc = 0; kc < N / 16; kc++) {
        uint32_t ah[4], al[4];
        LDSM_X4(ah, aH + kc * 32);
        LDSM_X4(al, aL + kc * 32);
#pragma unroll
        for (int nt = 0; nt < 4; nt++) {
            uint32_t bh[2], bl[2];
            LDSM_X2_T(bh, bH + (uint32_t)(kc * 32 * SDZ) + nt * 16);
            LDSM_X2_T(bl, bL + (uint32_t)(kc * 32 * SDZ) + nt * 16);
            MMA_BF16(acc[nt], ah, bh);
            MMA_BF16(acc[nt], ah, bl);
            MMA_BF16(acc[nt], al, bh);
        }
    }

    {
        const int f = f0 + fr;
        const int t0 = m0 + (lane >> 2);
        const int c0 = 2 * (lane & 3);
#pragma unroll
        for (int nt = 0; nt < 4; nt++) {
            int o = nt * 8 + c0;
            float2 bv = *reinterpret_cast<const float2*>(bias + OOFF + o);
            *reinterpret_cast<float2*>(out + ((size_t)f * N + t0) * 96 + OOFF + o) =
                make_float2(acc[nt][0] + bv.x, acc[nt][1] + bv.y);
            *reinterpret_cast<float2*>(out + ((size_t)f * N + t0 + 8) * 96 + OOFF + o) =
                make_float2(acc[nt][2] + bv.x, acc[nt][3] + bv.y);
        }
    }
}

__global__ __launch_bounds__(256) void k_stage3_a(float* __restrict__ out, const float* __restrict__ bias) {
    if (blockIdx.y == 0) stage3_body<32, 0, 0, 0>(out, bias);
    else stage3_body<64, 1024, 2228224, 32>(out, bias);
}
__global__ __launch_bounds__(256) void k_stage3_b(float* __restrict__ out, const float* __restrict__ bias) {
    stage3_body<128, 5120, 4390912, 64>(out, bias);
}

// ---------------- launch ----------------
extern "C" void kernel_launch(void* const* d_in, const int* in_sizes, int n_in,
                              void* d_out, int out_size) {
    const float* x    = (const float*)d_in[0];
    const float* kr   = (const float*)d_in[1];
    const float* ki   = (const float*)d_in[2];
    const float* bias = (const float*)d_in[3];
    float* out = (float*)d_out;

    const int s1_a = (2 * 64 * 72 + 2 * 128 * 72) * 2;    // 55296
    const int s1_b = (2 * 128 * 136 + 2 * 128 * 72) * 2;  // 106496
    const int s2   = (64 * 136 * 2) * 2;                  // 34816
    const int s3_a = (2 * 64 * 72 + 2 * 128 * 40) * 2;    // 38912
    const int s3_b = (2 * 128 * 136 + 2 * 128 * 40) * 2;  // 90112

    cudaFuncSetAttribute(k_stage1_a, cudaFuncAttributeMaxDynamicSharedMemorySize, s1_a);
    cudaFuncSetAttribute(k_stage1_b, cudaFuncAttributeMaxDynamicSharedMemorySize, s1_b);
    cudaFuncSetAttribute(k_stage2_tc, cudaFuncAttributeMaxDynamicSharedMemorySize, s2);
    cudaFuncSetAttribute(k_stage3_a, cudaFuncAttributeMaxDynamicSharedMemorySize, s3_a);
    cudaFuncSetAttribute(k_stage3_b, cudaFuncAttributeMaxDynamicSharedMemorySize, s3_b);

    k_build<<<dim3(584, 3), 256>>>(kr, ki);

    k_stage1_a<<<dim3(512, 2), 256, s1_a>>>(x);
    k_stage1_b<<<512, 256, s1_b>>>(x);

    k_stage2_tc<<<796, 256, s2>>>();

    k_stage3_a<<<dim3(512, 2), 256, s3_a>>>(out, bias);
    k_stage3_b<<<512, 256, s3_b>>>(out, bias);
}

// round 16
// speedup vs baseline: 1.1831x; 1.0927x over previous
#include <cuda_runtime.h>
#include <cuda_bf16.h>
#include <math.h>
#include <cstdint>

#define CIN 64
#define COUT_PER 32
#define LALPHA 0.2f

__device__ __forceinline__ float lk(float v) { return v > 0.f ? v : LALPHA * v; }

__device__ __forceinline__ uint32_t smem_u32(const void* p) {
    uint32_t a;
    asm("{ .reg .u64 t; cvta.to.shared.u64 t, %1; cvt.u32.u64 %0, t; }" : "=r"(a) : "l"(p));
    return a;
}
__device__ __forceinline__ uint32_t pkbf(float x, float y) {
    __nv_bfloat162 h = __floats2bfloat162_rn(x, y);
    return *reinterpret_cast<uint32_t*>(&h);
}
// pack fp32 -> (lo16<<16)|hi16 split-bf16
__device__ __forceinline__ uint32_t pksp(float v) {
    __nv_bfloat16 h = __float2bfloat16(v);
    float hf = __bfloat162float(h);
    __nv_bfloat16 l = __float2bfloat16(v - hf);
    uint16_t hb = *reinterpret_cast<uint16_t*>(&h);
    uint16_t lb = *reinterpret_cast<uint16_t*>(&l);
    return ((uint32_t)lb << 16) | hb;
}
__device__ __forceinline__ uint32_t hiperm(uint32_t a, uint32_t b) { return __byte_perm(a, b, 0x5410); }
__device__ __forceinline__ uint32_t loperm(uint32_t a, uint32_t b) { return __byte_perm(a, b, 0x7632); }

#define LDSM_X4(R, ADDR) \
    asm volatile("ldmatrix.sync.aligned.m8n8.x4.shared.b16 {%0,%1,%2,%3}, [%4];" \
        : "=r"((R)[0]), "=r"((R)[1]), "=r"((R)[2]), "=r"((R)[3]) : "r"(ADDR))
#define LDSM_X2_T(R, ADDR) \
    asm volatile("ldmatrix.sync.aligned.m8n8.x2.trans.shared.b16 {%0,%1}, [%2];" \
        : "=r"((R)[0]), "=r"((R)[1]) : "r"(ADDR))
#define MMA_BF16(ACC, A, B) \
    asm volatile("mma.sync.aligned.m16n8k16.row.col.f32.bf16.bf16.f32 " \
        "{%0,%1,%2,%3}, {%4,%5,%6,%7}, {%8,%9}, {%0,%1,%2,%3};" \
        : "+f"((ACC)[0]), "+f"((ACC)[1]), "+f"((ACC)[2]), "+f"((ACC)[3]) \
        : "r"((A)[0]), "r"((A)[1]), "r"((A)[2]), "r"((A)[3]), "r"((B)[0]), "r"((B)[1]))

// ---------------- static device scratch ----------------
// packed split-bf16 compact DFT tables; elem offs: fft32->0, fft64->1024, fft128->5120
__device__ __align__(16) uint32_t g_Dp[21504];
__device__ __align__(16) uint32_t g_Cp[21504];
// GT hi/lo bf16 [k][o2(64)][j(128)]; elem offs 0 / 139264 / 409600
__device__ __align__(16) __nv_bfloat16 g_Gh[942080];
__device__ __align__(16) __nv_bfloat16 g_Gl[942080];
// X packed split-bf16 [k][f][ri][c]; offs 0 / 4456448 / 8781824
__device__ __align__(16) uint32_t g_X[13041664];
// Z packed split-bf16 [f][j=2k+ri][o]; offs 0 / 2228224 / 4390912
__device__ __align__(16) uint32_t g_Z[6520832];

// ---------------- merged precompute ----------------
__global__ void k_build(const float* __restrict__ kr, const float* __restrict__ ki) {
    const int ffti = blockIdx.y;
    const int N = 32 << ffti;
    const int bins = N / 2 + 1;
    const int tid = threadIdx.x;
    if (blockIdx.x < 64) {
        int off = (ffti == 0) ? 0 : (ffti == 1 ? 1024 : 5120);
        int total = N * N;
        int stride = 64 * 256;
        for (int idx = blockIdx.x * 256 + tid; idx < total; idx += stride) {
            {   // D compact [rp][t], ra = rp + (rp>0)
                int rp = idx / N, t = idx % N;
                int ra = rp + (rp > 0);
                int k = ra >> 1, ri = ra & 1;
                int m = (k * t) % N;
                float s, c;
                sincospif(2.0f * (float)m / (float)N, &s, &c);
                g_Dp[off + idx] = pksp(ri ? -s : c);
            }
            {   // C compact [t][jj], ja = jj + (jj>0)
                int t = idx / N, jj = idx % N;
                int ja = jj + (jj > 0);
                int k = ja >> 1, ri = ja & 1;
                int m = (k * t) % N;
                float s, c;
                sincospif(2.0f * (float)m / (float)N, &s, &c);
                float w = (k == 0 || k == bins - 1) ? 1.0f : 2.0f;
                g_Cp[off + idx] = pksp((ri ? -s : c) * (w / (float)N));
            }
        }
    } else {
        int goff = (ffti == 0) ? 0 : (ffti == 1 ? 139264 : 409600);
        int total = bins * CIN * COUT_PER;
        int stride = 520 * 256;
        for (int idx = (blockIdx.x - 64) * 256 + tid; idx < total; idx += stride) {
            int k = idx / (CIN * COUT_PER);
            int rem = idx % (CIN * COUT_PER);
            int c = rem / COUT_PER, o = rem % COUT_PER;
            float vr, vi;
            if (bins == 33) {
                vr = kr[k * 2048 + rem];
                vi = ki[k * 2048 + rem];
            } else {
                float src = (k + 0.5f) * (33.0f / (float)bins) - 0.5f;
                float fl = floorf(src);
                int i0 = (int)fl;
                float f = src - fl;
                int i0c = i0 < 0 ? 0 : i0;
                int i1c = i0 + 1 > 32 ? 32 : i0 + 1;
                vr = (1.0f - f) * kr[i0c * 2048 + rem] + f * kr[i1c * 2048 + rem];
                vi = (1.0f - f) * ki[i0c * 2048 + rem] + f * ki[i1c * 2048 + rem];
            }
            int base = goff + k * 8192;
            auto st = [&](int pos, float v) {
                __nv_bfloat16 h = __float2bfloat16(v);
                g_Gh[pos] = h;
                g_Gl[pos] = __float2bfloat16(v - __bfloat162float(h));
            };
            st(base + (2 * o) * 128 + c, vr);
            st(base + (2 * o + 1) * 128 + c, vi);
            st(base + (2 * o) * 128 + 64 + c, -vi);
            st(base + (2 * o + 1) * 128 + 64 + c, vr);
        }
    }
}

// ---------------- stage 1 body: forward DFT, A direct from packed global D --------
template <int N, int DOFF, int XOFF, int F>
__device__ __forceinline__ void stage1_body(const float* __restrict__ x) {
    constexpr int RG = N / 16;
    constexpr int SDX = 72;
    extern __shared__ char smem[];
    __nv_bfloat16* Xh = reinterpret_cast<__nv_bfloat16*>(smem);
    __nv_bfloat16* Xl = Xh + 128 * SDX;

    const int tid = threadIdx.x;
    const int warp = tid >> 5, lane = tid & 31;
    const int f0 = blockIdx.x * (128 / N);

    // load + split x frames ([t][c] layout, 128 rows total)
    const float4* xg = reinterpret_cast<const float4*>(x + (size_t)f0 * N * 64);
    for (int idx = tid; idx < 2048; idx += 256) {
        int row = idx >> 4, q = idx & 15;
        float4 v = xg[idx];
        float hx = __bfloat162float(__float2bfloat16(v.x));
        float hy = __bfloat162float(__float2bfloat16(v.y));
        float hz = __bfloat162float(__float2bfloat16(v.z));
        float hw = __bfloat162float(__float2bfloat16(v.w));
        *reinterpret_cast<uint2*>(&Xh[row * SDX + 4 * q]) =
            make_uint2(pkbf(v.x, v.y), pkbf(v.z, v.w));
        *reinterpret_cast<uint2*>(&Xl[row * SDX + 4 * q]) =
            make_uint2(pkbf(v.x - hx, v.y - hy), pkbf(v.z - hz, v.w - hw));
    }
    __syncthreads();

    const int fr = warp / RG, rg = warp % RG;
    const int m0 = rg * 16;

    float acc[8][4];
#pragma unroll
    for (int nt = 0; nt < 8; nt++)
#pragma unroll
        for (int q = 0; q < 4; q++) acc[nt][q] = 0.f;

    // A fragments direct from packed D table
    const uint32_t* Arow0 = g_Dp + DOFF + (m0 + (lane >> 2)) * N + 2 * (lane & 3);
    const uint32_t* Arow1 = Arow0 + 8 * N;
    const uint32_t bH = smem_u32(Xh) + 2u * ((fr * N + (lane & 15)) * SDX);
    const uint32_t bL = bH + 2u * 128 * SDX;

    uint2 p[4];
    p[0] = *reinterpret_cast<const uint2*>(Arow0);
    p[1] = *reinterpret_cast<const uint2*>(Arow1);
    p[2] = *reinterpret_cast<const uint2*>(Arow0 + 8);
    p[3] = *reinterpret_cast<const uint2*>(Arow1 + 8);

#pragma unroll
    for (int kc = 0; kc < N / 16; kc++) {
        uint32_t ah[4], al[4];
#pragma unroll
        for (int q = 0; q < 4; q++) {
            ah[q] = hiperm(p[q].x, p[q].y);
            al[q] = loperm(p[q].x, p[q].y);
        }
        if (kc < N / 16 - 1) {
            p[0] = *reinterpret_cast<const uint2*>(Arow0 + 16 * (kc + 1));
            p[1] = *reinterpret_cast<const uint2*>(Arow1 + 16 * (kc + 1));
            p[2] = *reinterpret_cast<const uint2*>(Arow0 + 16 * (kc + 1) + 8);
            p[3] = *reinterpret_cast<const uint2*>(Arow1 + 16 * (kc + 1) + 8);
        }
#pragma unroll
        for (int nt = 0; nt < 8; nt++) {
            uint32_t bh[2], bl[2];
            LDSM_X2_T(bh, bH + (uint32_t)(kc * 32 * SDX) + nt * 16);
            LDSM_X2_T(bl, bL + (uint32_t)(kc * 32 * SDX) + nt * 16);
            MMA_BF16(acc[nt], ah, bh);
            MMA_BF16(acc[nt], ah, bl);
            MMA_BF16(acc[nt], al, bh);
        }
    }

    // epilogue: pack split-bf16 into X
    {
        const int f = f0 + fr;
        const int rp0 = m0 + (lane >> 2);
        const int c0 = 2 * (lane & 3);
#pragma unroll
        for (int nt = 0; nt < 8; nt++) {
            int c = nt * 8 + c0;
            {
                int ra = rp0 + (rp0 > 0);
                int k = ra >> 1, ri = ra & 1;
                *reinterpret_cast<uint2*>(
                    g_X + XOFF + ((size_t)(k * F + f) * 2 + ri) * 64 + c) =
                    make_uint2(pksp(acc[nt][0]), pksp(acc[nt][1]));
            }
            {
                int rp = rp0 + 8;
                int ra = rp + (rp > 0);
                int k = ra >> 1, ri = ra & 1;
                *reinterpret_cast<uint2*>(
                    g_X + XOFF + ((size_t)(k * F + f) * 2 + ri) * 64 + c) =
                    make_uint2(pksp(acc[nt][2]), pksp(acc[nt][3]));
            }
        }
    }

    if (tid < (128 / N) * 32) {
        int fr2 = tid >> 5, m = tid & 31;
        int kz = (m >> 4) ? (N / 2) : 0;
        int q = m & 15;
        *reinterpret_cast<uint4*>(
            g_X + XOFF + ((size_t)(kz * F + f0 + fr2) * 2 + 1) * 64 + 4 * q) =
            make_uint4(0u, 0u, 0u, 0u);
    }
}

__global__ __launch_bounds__(256) void k_stage1(const float* __restrict__ x) {
    if (blockIdx.y == 0) stage1_body<32, 0, 0, 2048>(x);
    else if (blockIdx.y == 1) stage1_body<64, 1024, 4456448, 1024>(x);
    else stage1_body<128, 5120, 8781824, 512>(x);
}

// ---------------- stage 2: mma.sync, A from global, B via LDSM_X4 pairs ----------
__global__ __launch_bounds__(256) void k_stage2_tc() {
    constexpr int SDB = 136;
    extern __shared__ char smem[];
    __nv_bfloat16* Bh = reinterpret_cast<__nv_bfloat16*>(smem);
    __nv_bfloat16* Bl = Bh + 64 * SDB;

    const int tid = threadIdx.x;
    const int warp = tid >> 5, lane = tid & 31;

    // segment decode: 16x17 | 8x33 | 4x65
    int b = blockIdx.x;
    int xoff, goff, zoff, F, bins, fb, k;
    if (b < 272) {
        fb = b / 17; k = b % 17;
        xoff = 0; goff = 0; zoff = 0; F = 2048; bins = 17;
    } else if (b < 536) {
        int t = b - 272;
        fb = t / 33; k = t % 33;
        xoff = 4456448; goff = 139264; zoff = 2228224; F = 1024; bins = 33;
    } else {
        int t = b - 536;
        fb = t / 65; k = t % 65;
        xoff = 8781824; goff = 409600; zoff = 4390912; F = 512; bins = 65;
    }
    const int f0 = fb * 128;

    // B: straight copy of pre-split G into smem
    const uint4* GhG = reinterpret_cast<const uint4*>(g_Gh + goff + (size_t)k * 8192);
    const uint4* GlG = reinterpret_cast<const uint4*>(g_Gl + goff + (size_t)k * 8192);
    for (int idx = tid; idx < 64 * 16; idx += 256) {
        int row = idx >> 4, q = idx & 15;
        *reinterpret_cast<uint4*>(&Bh[row * SDB + 8 * q]) = GhG[idx];
        *reinterpret_cast<uint4*>(&Bl[row * SDB + 8 * q]) = GlG[idx];
    }
    __syncthreads();

    const int m0 = warp * 16;
    float acc[8][4];
#pragma unroll
    for (int nt = 0; nt < 8; nt++)
#pragma unroll
        for (int q = 0; q < 4; q++) acc[nt][q] = 0.f;

    const uint32_t* Arow0 = g_X + xoff + ((size_t)k * F + f0 + m0 + (lane >> 2)) * 128 + 2 * (lane & 3);
    const uint32_t* Arow1 = Arow0 + 8 * 128;

    // x4 B addressing: lanes 0-7 -> n-rows 0-7 @k0, 8-15 -> @k+8, 16-23 -> n+8 @k0, 24-31 -> n+8 @k+8
    const uint32_t b4off = (uint32_t)(((lane & 7) + ((lane >> 4) << 3)) * SDB + (((lane >> 3) & 1) << 3));
    const uint32_t b4h = smem_u32(Bh) + 2 * b4off;
    const uint32_t b4l = smem_u32(Bl) + 2 * b4off;

    uint2 p[4];
    p[0] = *reinterpret_cast<const uint2*>(Arow0);
    p[1] = *reinterpret_cast<const uint2*>(Arow1);
    p[2] = *reinterpret_cast<const uint2*>(Arow0 + 8);
    p[3] = *reinterpret_cast<const uint2*>(Arow1 + 8);

#pragma unroll
    for (int kc = 0; kc < 8; kc++) {
        uint32_t ah[4], al[4];
#pragma unroll
        for (int q = 0; q < 4; q++) {
            ah[q] = hiperm(p[q].x, p[q].y);
            al[q] = loperm(p[q].x, p[q].y);
        }
        if (kc < 7) {
            p[0] = *reinterpret_cast<const uint2*>(Arow0 + 16 * (kc + 1));
            p[1] = *reinterpret_cast<const uint2*>(Arow1 + 16 * (kc + 1));
            p[2] = *reinterpret_cast<const uint2*>(Arow0 + 16 * (kc + 1) + 8);
            p[3] = *reinterpret_cast<const uint2*>(Arow1 + 16 * (kc + 1) + 8);
        }
#pragma unroll
        for (int ntp = 0; ntp < 4; ntp++) {
            uint32_t bh[4], bl[4];
            LDSM_X4(bh, b4h + (uint32_t)(ntp * 16 * SDB * 2) + 32 * kc);
            LDSM_X4(bl, b4l + (uint32_t)(ntp * 16 * SDB * 2) + 32 * kc);
            MMA_BF16(acc[2 * ntp], ah, bh);
            MMA_BF16(acc[2 * ntp], ah, bl);
            MMA_BF16(acc[2 * ntp], al, bh);
            MMA_BF16(acc[2 * ntp + 1], ah, bh + 2);
            MMA_BF16(acc[2 * ntp + 1], ah, bl + 2);
            MMA_BF16(acc[2 * ntp + 1], al, bh + 2);
        }
    }

    // epilogue: leaky + pack split-bf16 into Z
    {
        const int o = (lane & 3);
        const int r0 = f0 + m0 + (lane >> 2);
        uint32_t* zp0 = g_Z + zoff + ((size_t)r0 * bins + k) * 64;
        uint32_t* zp1 = g_Z + zoff + ((size_t)(r0 + 8) * bins + k) * 64;
#pragma unroll
        for (int nt = 0; nt < 8; nt++) {
            int oo = nt * 4 + o;
            zp0[oo]      = pksp(lk(acc[nt][0]));
            zp0[32 + oo] = pksp(lk(acc[nt][1]));
            zp1[oo]      = pksp(lk(acc[nt][2]));
            zp1[32 + oo] = pksp(lk(acc[nt][3]));
        }
    }
}

// ---------------- stage 3 body: irfft + bias, A direct from packed global C ------
template <int N, int COFF, int ZOFF, int OOFF>
__device__ __forceinline__ void stage3_body(float* __restrict__ out, const float* __restrict__ bias) {
    constexpr int BINS = N / 2 + 1;
    constexpr int RG = N / 16;
    constexpr int SDZ = 40;
    extern __shared__ char smem[];
    __nv_bfloat16* Zh = reinterpret_cast<__nv_bfloat16*>(smem);
    __nv_bfloat16* Zl = Zh + 128 * SDZ;

    const int tid = threadIdx.x;
    const int warp = tid >> 5, lane = tid & 31;
    const int f0 = blockIdx.x * (128 / N);

    // unpack packed Z with zero-col remap (compact row jj <- actual ja)
    for (int idx = tid; idx < 1024; idx += 256) {
        int row = idx >> 3, q = idx & 7;
        int fr = row / N, jj = row % N;
        int ja = jj + (jj > 0);
        uint4 p = *reinterpret_cast<const uint4*>(
            g_Z + ZOFF + (size_t)(f0 + fr) * (BINS * 64) + ja * 32 + 4 * q);
        *reinterpret_cast<uint2*>(&Zh[row * SDZ + 4 * q]) =
            make_uint2(hiperm(p.x, p.y), hiperm(p.z, p.w));
        *reinterpret_cast<uint2*>(&Zl[row * SDZ + 4 * q]) =
            make_uint2(loperm(p.x, p.y), loperm(p.z, p.w));
    }
    __syncthreads();

    const int fr = warp / RG, rg = warp % RG;
    const int m0 = rg * 16;

    float acc[4][4];
#pragma unroll
    for (int nt = 0; nt < 4; nt++)
#pragma unroll
        for (int q = 0; q < 4; q++) acc[nt][q] = 0.f;

    const uint32_t* Arow0 = g_Cp + COFF + (m0 + (lane >> 2)) * N + 2 * (lane & 3);
    const uint32_t* Arow1 = Arow0 + 8 * N;
    const uint32_t bH = smem_u32(Zh) + 2u * ((fr * N + (lane & 15)) * SDZ);
    const uint32_t bL = bH + 2u * 128 * SDZ;

    uint2 p[4];
    p[0] = *reinterpret_cast<const uint2*>(Arow0);
    p[1] = *reinterpret_cast<const uint2*>(Arow1);
    p[2] = *reinterpret_cast<const uint2*>(Arow0 + 8);
    p[3] = *reinterpret_cast<const uint2*>(Arow1 + 8);

#pragma unroll
    for (int kc = 0; kc < N / 16; kc++) {
        uint32_t ah[4], al[4];
#pragma unroll
        for (int q = 0; q < 4; q++) {
            ah[q] = hiperm(p[q].x, p[q].y);
            al[q] = loperm(p[q].x, p[q].y);
        }
        if (kc < N / 16 - 1) {
            p[0] = *reinterpret_cast<const uint2*>(Arow0 + 16 * (kc + 1));
            p[1] = *reinterpret_cast<const uint2*>(Arow1 + 16 * (kc + 1));
            p[2] = *reinterpret_cast<const uint2*>(Arow0 + 16 * (kc + 1) + 8);
            p[3] = *reinterpret_cast<const uint2*>(Arow1 + 16 * (kc + 1) + 8);
        }
#pragma unroll
        for (int nt = 0; nt < 4; nt++) {
            uint32_t bh[2], bl[2];
            LDSM_X2_T(bh, bH + (uint32_t)(kc * 32 * SDZ) + nt * 16);
            LDSM_X2_T(bl, bL + (uint32_t)(kc * 32 * SDZ) + nt * 16);
            MMA_BF16(acc[nt], ah, bh);
            MMA_BF16(acc[nt], ah, bl);
            MMA_BF16(acc[nt], al, bh);
        }
    }

    {
        const int f = f0 + fr;
        const int t0 = m0 + (lane >> 2);
        const int c0 = 2 * (lane & 3);
#pragma unroll
        for (int nt = 0; nt < 4; nt++) {
            int o = nt * 8 + c0;
            float2 bv = *reinterpret_cast<const float2*>(bias + OOFF + o);
            *reinterpret_cast<float2*>(out + ((size_t)f * N + t0) * 96 + OOFF + o) =
                make_float2(acc[nt][0] + bv.x, acc[nt][1] + bv.y);
            *reinterpret_cast<float2*>(out + ((size_t)f * N + t0 + 8) * 96 + OOFF + o) =
                make_float2(acc[nt][2] + bv.x, acc[nt][3] + bv.y);
        }
    }
}

__global__ __launch_bounds__(256) void k_stage3(float* __restrict__ out, const float* __restrict__ bias) {
    if (blockIdx.y == 0) stage3_body<32, 0, 0, 0>(out, bias);
    else if (blockIdx.y == 1) stage3_body<64, 1024, 2228224, 32>(out, bias);
    else stage3_body<128, 5120, 4390912, 64>(out, bias);
}

// ---------------- launch ----------------
extern "C" void kernel_launch(void* const* d_in, const int* in_sizes, int n_in,
                              void* d_out, int out_size) {
    const float* x    = (const float*)d_in[0];
    const float* kr   = (const float*)d_in[1];
    const float* ki   = (const float*)d_in[2];
    const float* bias = (const float*)d_in[3];
    float* out = (float*)d_out;

    const int s1 = 2 * 128 * 72 * 2;   // 36864
    const int s2 = 64 * 136 * 2 * 2;   // 34816
    const int s3 = 2 * 128 * 40 * 2;   // 20480

    k_build<<<dim3(584, 3), 256>>>(kr, ki);
    k_stage1<<<dim3(512, 3), 256, s1>>>(x);
    k_stage2_tc<<<796, 256, s2>>>();
    k_stage3<<<dim3(512, 3), 256, s3>>>(out, bias);
}